// round 5
// baseline (speedup 1.0000x reference)
#include <cuda_runtime.h>
#include <cuda_fp16.h>
#include <cstdint>

#define NNODES 100000
#define NEDGES 3200000
#define INDIM 256
#define HID 64
#define OUTD 32
#define NSCANB 98   // ceil(100000/1024)

// ---------------- scratch ----------------
__device__ __align__(128) int      g_deg[NNODES];
__device__ __align__(128) float    g_dinv[NNODES];
__device__ __align__(128) int      g_rowptr[NNODES + 1];
__device__ __align__(128) int      g_cursor[NNODES];
__device__ __align__(128) int      g_bsum[NSCANB];
__device__ __align__(128) uint64_t g_csr[NEDGES];                 // (norm_bits<<32) | src
__device__ __align__(128) __half   g_h1[(size_t)NNODES * HID];    // fp16 features for gather
__device__ __align__(128) float    g_h1r[(size_t)NNODES * HID];   // fp32 (GEMM2 input)
__device__ __align__(128) __half   g_h2[(size_t)NNODES * OUTD];
__device__ int g_is64;

// ---------------- init: zero degree + detect index dtype ----------------
__global__ void k_init(const int* __restrict__ ei32) {
    int i = blockIdx.x * blockDim.x + threadIdx.x;
    if (i < NNODES) g_deg[i] = 0;
    if (blockIdx.x == 0 && threadIdx.x == 0) {
        // int64 indices (<1e5) have all-zero odd 32-bit words
        int acc = 0;
        for (int k = 0; k < 512; k++) acc |= ei32[2 * k + 1];
        for (int k = 0; k < 512; k++) acc |= ei32[2 * (NEDGES / 2 + k) + 1];
        g_is64 = (acc == 0) ? 1 : 0;
    }
}

__device__ __forceinline__ void load_edge(const void* ei, int e, int& s, int& d) {
    if (g_is64) {
        const long long* p = (const long long*)ei;
        s = (int)p[e];
        d = (int)p[NEDGES + e];
    } else {
        const int* p = (const int*)ei;
        s = p[e];
        d = p[NEDGES + e];
    }
}

__global__ void k_count(const void* __restrict__ ei) {
    int e = blockIdx.x * blockDim.x + threadIdx.x;
    if (e >= NEDGES) return;
    int s, d;
    load_edge(ei, e, s, d);
    atomicAdd(&g_deg[d], 1);
}

// ---------------- exclusive scan of g_deg -> g_rowptr ----------------
__global__ void k_scan_block() {
    __shared__ int s[1024];
    int t = threadIdx.x;
    int gi = blockIdx.x * 1024 + t;
    int v = (gi < NNODES) ? g_deg[gi] : 0;
    s[t] = v;
    __syncthreads();
#pragma unroll
    for (int off = 1; off < 1024; off <<= 1) {
        int a = (t >= off) ? s[t - off] : 0;
        __syncthreads();
        s[t] += a;
        __syncthreads();
    }
    if (gi <= NNODES) g_rowptr[gi] = s[t] - v;  // exclusive (block-local)
    if (t == 1023) g_bsum[blockIdx.x] = s[1023];
}

__global__ void k_scan_top() {
    if (threadIdx.x == 0) {
        int run = 0;
        for (int i = 0; i < NSCANB; i++) { int t = g_bsum[i]; g_bsum[i] = run; run += t; }
    }
}

// finalize rowptr, init cursor, compute dinv (merged)
__global__ void k_scan_add() {
    int i = blockIdx.x * blockDim.x + threadIdx.x;
    if (i < NNODES) {
        int rp = g_rowptr[i] + g_bsum[i >> 10];
        g_rowptr[i] = rp;
        g_cursor[i] = rp;
        g_dinv[i]   = rsqrtf((float)g_deg[i] + 1.0f);  // +1 self loop
    }
    if (i == 0) g_rowptr[NNODES] = NEDGES;
}

// ---------------- fill CSR: packed (norm, src) per edge, grouped by dst ----------------
__global__ void k_fill(const void* __restrict__ ei) {
    int e = blockIdx.x * blockDim.x + threadIdx.x;
    if (e >= NEDGES) return;
    int s, d;
    load_edge(ei, e, s, d);
    int pos = atomicAdd(&g_cursor[d], 1);
    float nrm = g_dinv[s] * g_dinv[d];
    g_csr[pos] = ((uint64_t)__float_as_uint(nrm) << 32) | (uint32_t)s;
}

// ---------------- GEMM: Hh[M,NO] = X[M,K] @ W[K,NO], f32x2 FMA, fp16 output ----------------
// 256 threads; CG = NO/16 column groups (warp-uniform); ROWS rows per thread,
// strided by TPG (rows r + i*TPG). Scalar x reads (alignment-safe), broadcast w reads.
template <int K, int NO, int ROWS>
__global__ void __launch_bounds__(256) k_gemm(const float* __restrict__ X,
                                              const float* __restrict__ W,
                                              __half* __restrict__ Hh) {
    constexpr int KT  = 32;
    constexpr int CG  = NO / 16;
    constexpr int TPG = 256 / CG;       // threads per column group
    constexpr int RR  = TPG * ROWS;     // rows per block

    __shared__ __align__(16) float xs[RR * (KT + 1)];   // row-major, pad -> conflict-free
    __shared__ __align__(16) float ws[KT * NO];

    const int tid  = threadIdx.x;
    const int r    = tid % TPG;
    const int cg   = tid / TPG;         // warp-uniform
    const int row0 = blockIdx.x * RR;

    uint64_t acc[ROWS][8];
#pragma unroll
    for (int i = 0; i < ROWS; i++)
#pragma unroll
        for (int p = 0; p < 8; p++) acc[i][p] = 0;

    for (int kt = 0; kt < K; kt += KT) {
        for (int idx = tid; idx < RR * KT; idx += 256) {
            int rr = idx / KT, kk = idx % KT;   // consecutive tid -> consecutive kk (coalesced gmem)
            int gr = row0 + rr;
            xs[rr * (KT + 1) + kk] = (gr < NNODES) ? X[(size_t)gr * K + kt + kk] : 0.0f;
        }
        for (int idx = tid; idx < KT * NO; idx += 256)
            ws[idx] = W[(size_t)kt * NO + idx];
        __syncthreads();

#pragma unroll
        for (int k = 0; k < KT; k++) {
            uint64_t xd[ROWS];
#pragma unroll
            for (int i = 0; i < ROWS; i++) {
                float xv = xs[(r + i * TPG) * (KT + 1) + k];
                asm("mov.b64 %0, {%1, %1};" : "=l"(xd[i]) : "f"(xv));
            }
            const uint64_t* wrow = reinterpret_cast<const uint64_t*>(&ws[k * NO + cg * 16]);
#pragma unroll
            for (int p = 0; p < 8; p++) {
                uint64_t w = wrow[p];   // broadcast LDS.64 (warp-uniform address)
#pragma unroll
                for (int i = 0; i < ROWS; i++)
                    asm("fma.rn.f32x2 %0, %1, %2, %0;" : "+l"(acc[i][p]) : "l"(xd[i]), "l"(w));
            }
        }
        __syncthreads();
    }

#pragma unroll
    for (int i = 0; i < ROWS; i++) {
        int row = row0 + r + i * TPG;
        if (row < NNODES) {
            uint32_t hv[8];
#pragma unroll
            for (int p = 0; p < 8; p++) {
                float lo, hi;
                asm("mov.b64 {%0, %1}, %2;" : "=f"(lo), "=f"(hi) : "l"(acc[i][p]));
                __half2 h2v = __floats2half2_rn(lo, hi);
                hv[p] = *reinterpret_cast<uint32_t*>(&h2v);
            }
            uint4* o = reinterpret_cast<uint4*>(&Hh[(size_t)row * NO + cg * 16]);
            o[0] = make_uint4(hv[0], hv[1], hv[2], hv[3]);
            o[1] = make_uint4(hv[4], hv[5], hv[6], hv[7]);
        }
    }
}

// ---------------- gather-side aggregation (no atomics) ----------------
// layer 1: warp per node, lane owns 2 cols (fp16 gather). Fuses self-loop, bias, ReLU.
__global__ void __launch_bounds__(256) k_agg1(const float* __restrict__ b1,
                                              float* __restrict__ h1r) {
    int node = blockIdx.x * 8 + (threadIdx.x >> 5);
    if (node >= NNODES) return;
    int lane = threadIdx.x & 31;
    int beg = g_rowptr[node], end = g_rowptr[node + 1];
    float dn = g_dinv[node];
    float sc = dn * dn;
    float2 hv = __half22float2(*reinterpret_cast<const __half2*>(&g_h1[(size_t)node * HID + lane * 2]));
    float2 bv = *reinterpret_cast<const float2*>(&b1[lane * 2]);
    float2 acc = make_float2(fmaf(sc, hv.x, bv.x), fmaf(sc, hv.y, bv.y));
#pragma unroll 4
    for (int j = beg; j < end; j++) {
        uint64_t q = g_csr[j];                     // broadcast across warp
        int s = (int)(uint32_t)q;
        float nrm = __uint_as_float((uint32_t)(q >> 32));
        float2 vv = __half22float2(*reinterpret_cast<const __half2*>(&g_h1[(size_t)s * HID + lane * 2]));
        acc.x = fmaf(nrm, vv.x, acc.x);
        acc.y = fmaf(nrm, vv.y, acc.y);
    }
    *reinterpret_cast<float2*>(&h1r[(size_t)node * HID + lane * 2]) =
        make_float2(fmaxf(acc.x, 0.0f), fmaxf(acc.y, 0.0f));
}

// layer 2: warp per node, lane owns 1 col. Fuses self-loop + bias.
__global__ void __launch_bounds__(256) k_agg2(const float* __restrict__ b2,
                                              float* __restrict__ out) {
    int node = blockIdx.x * 8 + (threadIdx.x >> 5);
    if (node >= NNODES) return;
    int lane = threadIdx.x & 31;
    int beg = g_rowptr[node], end = g_rowptr[node + 1];
    float dn = g_dinv[node];
    float acc = fmaf(dn * dn, __half2float(g_h2[(size_t)node * OUTD + lane]), b2[lane]);
#pragma unroll 4
    for (int j = beg; j < end; j++) {
        uint64_t q = g_csr[j];
        int s = (int)(uint32_t)q;
        float nrm = __uint_as_float((uint32_t)(q >> 32));
        acc = fmaf(nrm, __half2float(g_h2[(size_t)s * OUTD + lane]), acc);
    }
    out[(size_t)node * OUTD + lane] = acc;
}

// ---------------- launch ----------------
extern "C" void kernel_launch(void* const* d_in, const int* in_sizes, int n_in,
                              void* d_out, int out_size) {
    const float* x  = (const float*)d_in[0];
    const void*  ei = d_in[1];
    const float* W1 = (const float*)d_in[2];
    const float* b1 = (const float*)d_in[3];
    const float* W2 = (const float*)d_in[4];
    const float* b2 = (const float*)d_in[5];
    float*       out = (float*)d_out;

    void *ph1, *ph1r, *ph2;
    cudaGetSymbolAddress(&ph1,  g_h1);
    cudaGetSymbolAddress(&ph1r, g_h1r);
    cudaGetSymbolAddress(&ph2,  g_h2);
    __half* h1  = (__half*)ph1;
    float*  h1r = (float*)ph1r;
    __half* h2  = (__half*)ph2;

    const int NT = 256;
    const int EB = (NEDGES + NT - 1) / NT;
    const int NB = (NNODES + NT - 1) / NT;

    // graph normalization + CSR build
    k_init<<<NB, NT>>>((const int*)ei);
    k_count<<<EB, NT>>>(ei);
    k_scan_block<<<NSCANB, 1024>>>();
    k_scan_top<<<1, 32>>>();
    k_scan_add<<<NB, NT>>>();
    k_fill<<<EB, NT>>>(ei);

    // layer 1: h1 = fp16(X @ W1) ; h1r = relu(selfloop + b1 + gather)
    k_gemm<INDIM, HID, 4><<<(NNODES + 255) / 256, NT>>>(x, W1, h1);
    k_agg1<<<(NNODES + 7) / 8, NT>>>(b1, h1r);

    // layer 2: h2 = fp16(h1r @ W2) ; out = selfloop + b2 + gather
    k_gemm<HID, OUTD, 2><<<(NNODES + 255) / 256, NT>>>(h1r, W2, h2);
    k_agg2<<<(NNODES + 7) / 8, NT>>>(b2, out);
}

// round 6
// speedup vs baseline: 1.1117x; 1.1117x over previous
#include <cuda_runtime.h>
#include <cuda_fp16.h>
#include <cstdint>

#define NNODES 100000
#define NEDGES 3200000
#define INDIM 256
#define HID 64
#define OUTD 32
#define NSCANB 98   // ceil(100000/1024)

// ---------------- scratch ----------------
__device__ __align__(128) int      g_deg[NNODES];
__device__ __align__(128) float    g_dinv[NNODES];
__device__ __align__(128) int      g_rowptr[NNODES + 1];
__device__ __align__(128) int      g_cursor[NNODES];
__device__ __align__(128) int      g_bsum[NSCANB];
__device__ __align__(128) uint64_t g_csr[NEDGES];                 // (norm_bits<<32) | (src*128)
__device__ __align__(128) __half   g_h1[(size_t)NNODES * HID];    // fp16 features for gather
__device__ __align__(128) float    g_h1r[(size_t)NNODES * HID];   // fp32 (GEMM2 input)
__device__ __align__(128) __half   g_h2[(size_t)NNODES * OUTD];
__device__ int g_is64;

// ---------------- init: zero degree + detect index dtype ----------------
__global__ void k_init(const int* __restrict__ ei32) {
    int i = blockIdx.x * blockDim.x + threadIdx.x;
    if (i < NNODES) g_deg[i] = 0;
    if (blockIdx.x == 0 && threadIdx.x == 0) {
        int acc = 0;
        for (int k = 0; k < 512; k++) acc |= ei32[2 * k + 1];
        for (int k = 0; k < 512; k++) acc |= ei32[2 * (NEDGES / 2 + k) + 1];
        g_is64 = (acc == 0) ? 1 : 0;
    }
}

__device__ __forceinline__ void load_edge(const void* ei, int e, int& s, int& d) {
    if (g_is64) {
        const long long* p = (const long long*)ei;
        s = (int)p[e];
        d = (int)p[NEDGES + e];
    } else {
        const int* p = (const int*)ei;
        s = p[e];
        d = p[NEDGES + e];
    }
}

__global__ void k_count(const void* __restrict__ ei) {
    int e = blockIdx.x * blockDim.x + threadIdx.x;
    if (e >= NEDGES) return;
    int s, d;
    load_edge(ei, e, s, d);
    atomicAdd(&g_deg[d], 1);
}

// ---------------- exclusive scan of g_deg -> g_rowptr ----------------
__global__ void k_scan_block() {
    __shared__ int s[1024];
    int t = threadIdx.x;
    int gi = blockIdx.x * 1024 + t;
    int v = (gi < NNODES) ? g_deg[gi] : 0;
    s[t] = v;
    __syncthreads();
#pragma unroll
    for (int off = 1; off < 1024; off <<= 1) {
        int a = (t >= off) ? s[t - off] : 0;
        __syncthreads();
        s[t] += a;
        __syncthreads();
    }
    if (gi <= NNODES) g_rowptr[gi] = s[t] - v;
    if (t == 1023) g_bsum[blockIdx.x] = s[1023];
}

// warp shfl-scan over NSCANB block sums
__global__ void k_scan_top() {
    int lane = threadIdx.x;  // 32 threads
    int carry = 0;
    for (int base = 0; base < NSCANB; base += 32) {
        int i = base + lane;
        int v = (i < NSCANB) ? g_bsum[i] : 0;
        int x = v;
#pragma unroll
        for (int off = 1; off < 32; off <<= 1) {
            int y = __shfl_up_sync(0xffffffffu, x, off);
            if (lane >= off) x += y;
        }
        if (i < NSCANB) g_bsum[i] = x - v + carry;       // exclusive + carry
        carry += __shfl_sync(0xffffffffu, x, 31);
    }
}

// finalize rowptr, init cursor, compute dinv (merged)
__global__ void k_scan_add() {
    int i = blockIdx.x * blockDim.x + threadIdx.x;
    if (i < NNODES) {
        int rp = g_rowptr[i] + g_bsum[i >> 10];
        g_rowptr[i] = rp;
        g_cursor[i] = rp;
        g_dinv[i]   = rsqrtf((float)g_deg[i] + 1.0f);
    }
    if (i == 0) g_rowptr[NNODES] = NEDGES;
}

// ---------------- fill CSR: (norm, src*128) per edge, grouped by dst ----------------
__global__ void k_fill(const void* __restrict__ ei) {
    int e = blockIdx.x * blockDim.x + threadIdx.x;
    if (e >= NEDGES) return;
    int s, d;
    load_edge(ei, e, s, d);
    int pos = atomicAdd(&g_cursor[d], 1);
    float nrm = g_dinv[s] * g_dinv[d];
    g_csr[pos] = ((uint64_t)__float_as_uint(nrm) << 32) | (uint32_t)(s * 128);  // byte offset into g_h1
}

// ---------------- GEMM: Hh[M,NO] = X[M,K] @ W[K,NO], f32x2 FMA, fp16 out ----------------
// R3-proven config: 256 threads, CG=NO/16 col groups, 2 rows per thread strided by TPG.
template <int K, int NO>
__global__ void __launch_bounds__(256) k_gemm(const float* __restrict__ X,
                                              const float* __restrict__ W,
                                              __half* __restrict__ Hh) {
    constexpr int KT  = 32;
    constexpr int CG  = NO / 16;
    constexpr int TPG = 256 / CG;
    constexpr int RR  = TPG * 2;

    __shared__ __align__(16) float xs[RR * (KT + 1)];
    __shared__ __align__(16) float ws[KT * NO];

    const int tid  = threadIdx.x;
    const int r    = tid % TPG;
    const int cg   = tid / TPG;
    const int row0 = blockIdx.x * RR;

    uint64_t acc0[8], acc1[8];
#pragma unroll
    for (int p = 0; p < 8; p++) { acc0[p] = 0; acc1[p] = 0; }

    for (int kt = 0; kt < K; kt += KT) {
        for (int idx = tid; idx < RR * KT; idx += 256) {
            int rr = idx / KT, kk = idx % KT;
            int gr = row0 + rr;
            xs[rr * (KT + 1) + kk] = (gr < NNODES) ? X[(size_t)gr * K + kt + kk] : 0.0f;
        }
        for (int idx = tid; idx < KT * NO; idx += 256)
            ws[idx] = W[(size_t)kt * NO + idx];
        __syncthreads();

#pragma unroll
        for (int k = 0; k < KT; k++) {
            float xv0 = xs[r * (KT + 1) + k];
            float xv1 = xs[(r + TPG) * (KT + 1) + k];
            uint64_t xa, xb;
            asm("mov.b64 %0, {%1, %1};" : "=l"(xa) : "f"(xv0));
            asm("mov.b64 %0, {%1, %1};" : "=l"(xb) : "f"(xv1));
            const uint64_t* wrow = reinterpret_cast<const uint64_t*>(&ws[k * NO + cg * 16]);
#pragma unroll
            for (int p = 0; p < 8; p++) {
                uint64_t w = wrow[p];
                asm("fma.rn.f32x2 %0, %1, %2, %0;" : "+l"(acc0[p]) : "l"(xa), "l"(w));
                asm("fma.rn.f32x2 %0, %1, %2, %0;" : "+l"(acc1[p]) : "l"(xb), "l"(w));
            }
        }
        __syncthreads();
    }

#pragma unroll
    for (int i = 0; i < 2; i++) {
        int row = row0 + r + i * TPG;
        uint64_t* a = (i == 0) ? acc0 : acc1;
        if (row < NNODES) {
            uint32_t hv[8];
#pragma unroll
            for (int p = 0; p < 8; p++) {
                float lo, hi;
                asm("mov.b64 {%0, %1}, %2;" : "=f"(lo), "=f"(hi) : "l"(a[p]));
                __half2 h2v = __floats2half2_rn(lo, hi);
                hv[p] = *reinterpret_cast<uint32_t*>(&h2v);
            }
            uint4* o = reinterpret_cast<uint4*>(&Hh[(size_t)row * NO + cg * 16]);
            o[0] = make_uint4(hv[0], hv[1], hv[2], hv[3]);
            o[1] = make_uint4(hv[4], hv[5], hv[6], hv[7]);
        }
    }
}

// ---------------- gather aggregation: 2 warps per node, 8-wide batches ----------------
// layer 1: lane owns 2 cols. Fuses self-loop, bias, ReLU. 256 thr = 8 warps = 4 nodes.
__global__ void __launch_bounds__(256) k_agg1(const float* __restrict__ b1,
                                              float* __restrict__ h1r) {
    __shared__ float2 spart[4][32];
    int wid  = threadIdx.x >> 5;
    int node = blockIdx.x * 4 + (wid >> 1);      // NNODES % 4 == 0: always valid
    int half = wid & 1;
    int lane = threadIdx.x & 31;
    int beg = g_rowptr[node], end = g_rowptr[node + 1];
    int mid = (beg + end) >> 1;
    int lo = half ? mid : beg;
    int hi = half ? end : mid;

    const char* h1b = (const char*)g_h1;
    float2 acc = make_float2(0.0f, 0.0f);
    int j = lo;
    for (; j + 8 <= hi; j += 8) {
        uint64_t q[8];
#pragma unroll
        for (int t = 0; t < 8; t++) q[t] = g_csr[j + t];
#pragma unroll
        for (int t = 0; t < 8; t++) {
            float nrm = __uint_as_float((uint32_t)(q[t] >> 32));
            float2 vv = __half22float2(
                *reinterpret_cast<const __half2*>(h1b + (uint32_t)q[t] + lane * 4));
            acc.x = fmaf(nrm, vv.x, acc.x);
            acc.y = fmaf(nrm, vv.y, acc.y);
        }
    }
    for (; j < hi; j++) {
        uint64_t q = g_csr[j];
        float nrm = __uint_as_float((uint32_t)(q >> 32));
        float2 vv = __half22float2(
            *reinterpret_cast<const __half2*>(h1b + (uint32_t)q + lane * 4));
        acc.x = fmaf(nrm, vv.x, acc.x);
        acc.y = fmaf(nrm, vv.y, acc.y);
    }

    if (half) {
        spart[wid >> 1][lane] = acc;
    }
    __syncthreads();
    if (!half) {
        float dn = g_dinv[node];
        float sc = dn * dn;
        float2 hv = __half22float2(
            *reinterpret_cast<const __half2*>(&g_h1[(size_t)node * HID + lane * 2]));
        float2 bv = *reinterpret_cast<const float2*>(&b1[lane * 2]);
        float2 o = spart[wid >> 1][lane];
        acc.x += o.x + fmaf(sc, hv.x, bv.x);
        acc.y += o.y + fmaf(sc, hv.y, bv.y);
        *reinterpret_cast<float2*>(&h1r[(size_t)node * HID + lane * 2]) =
            make_float2(fmaxf(acc.x, 0.0f), fmaxf(acc.y, 0.0f));
    }
}

// layer 2: lane owns 1 col. Fuses self-loop + bias.
__global__ void __launch_bounds__(256) k_agg2(const float* __restrict__ b2,
                                              float* __restrict__ out) {
    __shared__ float spart[4][32];
    int wid  = threadIdx.x >> 5;
    int node = blockIdx.x * 4 + (wid >> 1);
    int half = wid & 1;
    int lane = threadIdx.x & 31;
    int beg = g_rowptr[node], end = g_rowptr[node + 1];
    int mid = (beg + end) >> 1;
    int lo = half ? mid : beg;
    int hi = half ? end : mid;

    const char* h2b = (const char*)g_h2;
    float acc = 0.0f;
    int j = lo;
    for (; j + 8 <= hi; j += 8) {
        uint64_t q[8];
#pragma unroll
        for (int t = 0; t < 8; t++) q[t] = g_csr[j + t];
#pragma unroll
        for (int t = 0; t < 8; t++) {
            float nrm = __uint_as_float((uint32_t)(q[t] >> 32));
            float v = __half2float(
                *reinterpret_cast<const __half*>(h2b + (((uint32_t)q[t]) >> 1) + lane * 2));
            acc = fmaf(nrm, v, acc);
        }
    }
    for (; j < hi; j++) {
        uint64_t q = g_csr[j];
        float nrm = __uint_as_float((uint32_t)(q >> 32));
        float v = __half2float(
            *reinterpret_cast<const __half*>(h2b + (((uint32_t)q) >> 1) + lane * 2));
        acc = fmaf(nrm, v, acc);
    }

    if (half) {
        spart[wid >> 1][lane] = acc;
    }
    __syncthreads();
    if (!half) {
        float dn = g_dinv[node];
        acc += spart[wid >> 1][lane];
        acc += fmaf(dn * dn, __half2float(g_h2[(size_t)node * OUTD + lane]), b2[lane]);
        out[(size_t)node * OUTD + lane] = acc;
    }
}

// ---------------- launch ----------------
extern "C" void kernel_launch(void* const* d_in, const int* in_sizes, int n_in,
                              void* d_out, int out_size) {
    const float* x  = (const float*)d_in[0];
    const void*  ei = d_in[1];
    const float* W1 = (const float*)d_in[2];
    const float* b1 = (const float*)d_in[3];
    const float* W2 = (const float*)d_in[4];
    const float* b2 = (const float*)d_in[5];
    float*       out = (float*)d_out;

    void *ph1, *ph1r, *ph2;
    cudaGetSymbolAddress(&ph1,  g_h1);
    cudaGetSymbolAddress(&ph1r, g_h1r);
    cudaGetSymbolAddress(&ph2,  g_h2);
    __half* h1  = (__half*)ph1;
    float*  h1r = (float*)ph1r;
    __half* h2  = (__half*)ph2;

    const int NT = 256;
    const int EB = (NEDGES + NT - 1) / NT;
    const int NB = (NNODES + NT - 1) / NT;

    // graph normalization + CSR build
    k_init<<<NB, NT>>>((const int*)ei);
    k_count<<<EB, NT>>>(ei);
    k_scan_block<<<NSCANB, 1024>>>();
    k_scan_top<<<1, 32>>>();
    k_scan_add<<<NB, NT>>>();
    k_fill<<<EB, NT>>>(ei);

    // layer 1
    k_gemm<INDIM, HID><<<(NNODES + 127) / 128, NT>>>(x, W1, h1);
    k_agg1<<<NNODES / 4, NT>>>(b1, h1r);

    // layer 2
    k_gemm<HID, OUTD><<<(NNODES + 255) / 256, NT>>>(h1r, W2, h2);
    k_agg2<<<NNODES / 4, NT>>>(b2, out);
}

// round 7
// speedup vs baseline: 1.2296x; 1.1061x over previous
#include <cuda_runtime.h>
#include <cuda_fp16.h>
#include <cstdint>

#define NNODES 100000
#define NEDGES 3200000
#define INDIM 256
#define HID 64
#define OUTD 32
#define NSCANB 98   // ceil(100000/1024)

// ---------------- scratch ----------------
__device__ __align__(128) int      g_deg[NNODES];
__device__ __align__(128) float    g_dinv[NNODES];
__device__ __align__(128) int      g_rowptr[NNODES + 1];
__device__ __align__(128) int      g_cursor[NNODES];
__device__ __align__(128) int      g_bsum[NSCANB];
__device__ __align__(128) uint64_t g_csr[NEDGES];                 // (norm_bits<<32) | (src*128)
__device__ __align__(128) __half   g_h1[(size_t)NNODES * HID];    // fp16 features for gather
__device__ __align__(128) float    g_h1r[(size_t)NNODES * HID];   // fp32 (GEMM2 input)
__device__ __align__(128) __half   g_h2[(size_t)NNODES * OUTD];
__device__ int g_is64;

// ---------------- init: zero degree + detect index dtype ----------------
__global__ void k_init(const int* __restrict__ ei32) {
    int i = blockIdx.x * blockDim.x + threadIdx.x;
    if (i < NNODES) g_deg[i] = 0;
    if (blockIdx.x == 0 && threadIdx.x == 0) {
        int acc = 0;
        for (int k = 0; k < 512; k++) acc |= ei32[2 * k + 1];
        for (int k = 0; k < 512; k++) acc |= ei32[2 * (NEDGES / 2 + k) + 1];
        g_is64 = (acc == 0) ? 1 : 0;
    }
}

__device__ __forceinline__ void load_edge(const void* ei, int e, int& s, int& d) {
    if (g_is64) {
        const long long* p = (const long long*)ei;
        s = (int)p[e];
        d = (int)p[NEDGES + e];
    } else {
        const int* p = (const int*)ei;
        s = p[e];
        d = p[NEDGES + e];
    }
}

__global__ void k_count(const void* __restrict__ ei) {
    int e = blockIdx.x * blockDim.x + threadIdx.x;
    if (e >= NEDGES) return;
    int s, d;
    load_edge(ei, e, s, d);
    atomicAdd(&g_deg[d], 1);
}

// ---------------- scan: per-block inclusive totals into g_bsum ----------------
__global__ void k_scan_block() {
    __shared__ int s[1024];
    int t = threadIdx.x;
    int gi = blockIdx.x * 1024 + t;
    int v = (gi < NNODES) ? g_deg[gi] : 0;
    s[t] = v;
    __syncthreads();
#pragma unroll
    for (int off = 1; off < 1024; off <<= 1) {
        int a = (t >= off) ? s[t - off] : 0;
        __syncthreads();
        s[t] += a;
        __syncthreads();
    }
    if (gi <= NNODES) g_rowptr[gi] = s[t] - v;   // exclusive, block-local
    if (t == 1023) g_bsum[blockIdx.x] = s[1023]; // raw block total
}

// finalize rowptr (+ cursor, dinv). Warp 0 reduces its prefix over g_bsum directly.
__global__ void k_scan_add() {
    __shared__ int spfx;
    int b = blockIdx.x;          // 1024-aligned with scan blocks
    int t = threadIdx.x;
    if (t < 32) {
        int s = 0;
        for (int i = t; i < b; i += 32) s += g_bsum[i];
#pragma unroll
        for (int off = 16; off > 0; off >>= 1) s += __shfl_xor_sync(0xffffffffu, s, off);
        if (t == 0) spfx = s;
    }
    __syncthreads();
    int i = b * 1024 + t;
    if (i < NNODES) {
        int rp = g_rowptr[i] + spfx;
        g_rowptr[i] = rp;
        g_cursor[i] = rp;
        g_dinv[i]   = rsqrtf((float)g_deg[i] + 1.0f);
    }
    if (i == 0) g_rowptr[NNODES] = NEDGES;
}

// ---------------- fill CSR: (norm, src*128) per edge, grouped by dst ----------------
__global__ void k_fill(const void* __restrict__ ei) {
    int e = blockIdx.x * blockDim.x + threadIdx.x;
    if (e >= NEDGES) return;
    int s, d;
    load_edge(ei, e, s, d);
    int pos = atomicAdd(&g_cursor[d], 1);
    float nrm = g_dinv[s] * g_dinv[d];
    g_csr[pos] = ((uint64_t)__float_as_uint(nrm) << 32) | (uint32_t)(s * 128);
}

// ---------------- GEMM1: g_h1 = fp16(X[100K,256] @ W1[256,64]), HMMA ----------------
// 256 threads = 8 warps; M-tile 128 (warp owns m16), N=64, K-tiles of 64.
// SW128 swizzle (bits[6:4] ^= row&7 <<4) for conflict-free ldmatrix.
#define SWZ(off) ((off) ^ (((off) >> 3) & 0x70))
__global__ void __launch_bounds__(256) k_gemm1(const float* __restrict__ X,
                                               const float* __restrict__ W,
                                               __half* __restrict__ Hh) {
    __shared__ __align__(16) __half xs[128 * 64];   // 16 KB, rows of 128B
    __shared__ __align__(16) __half wsm[64 * 64];   // 8 KB,  rows of 128B
    const int tid  = threadIdx.x;
    const int warp = tid >> 5;
    const int lane = tid & 31;
    const int row0 = blockIdx.x * 128;

    float acc[8][4];
#pragma unroll
    for (int n = 0; n < 8; n++)
#pragma unroll
        for (int q = 0; q < 4; q++) acc[n][q] = 0.0f;

    uint32_t xs_base  = (uint32_t)__cvta_generic_to_shared(xs);
    uint32_t wsm_base = (uint32_t)__cvta_generic_to_shared(wsm);

    for (int kt = 0; kt < 4; kt++) {           // K tiles of 64
        // X tile: 128 rows x 64 cols, fp32 -> fp16, swizzled
        for (int idx = tid; idx < 128 * 32; idx += 256) {
            int row = idx >> 5, cp = idx & 31;
            int gr = row0 + row;
            float2 v = (gr < NNODES)
                ? *reinterpret_cast<const float2*>(&X[(size_t)gr * INDIM + kt * 64 + cp * 2])
                : make_float2(0.0f, 0.0f);
            uint32_t off = SWZ((uint32_t)(row * 128 + cp * 4));
            *reinterpret_cast<__half2*>((char*)xs + off) = __floats2half2_rn(v.x, v.y);
        }
        // W tile: 64 rows x 64 cols
        for (int idx = tid; idx < 64 * 32; idx += 256) {
            int row = idx >> 5, cp = idx & 31;
            float2 v = *reinterpret_cast<const float2*>(&W[(size_t)(kt * 64 + row) * HID + cp * 2]);
            uint32_t off = SWZ((uint32_t)(row * 128 + cp * 4));
            *reinterpret_cast<__half2*>((char*)wsm + off) = __floats2half2_rn(v.x, v.y);
        }
        __syncthreads();

#pragma unroll
        for (int ks = 0; ks < 4; ks++) {       // k16 steps
            // A fragment: m16 x k16 at (warp*16, ks*16)
            uint32_t a0, a1, a2, a3;
            {
                uint32_t off = (uint32_t)((warp * 16 + (lane & 15)) * 128 + ks * 32 + (lane >> 4) * 16);
                uint32_t addr = xs_base + SWZ(off);
                asm volatile("ldmatrix.sync.aligned.m8n8.x4.shared.b16 {%0,%1,%2,%3}, [%4];"
                             : "=r"(a0), "=r"(a1), "=r"(a2), "=r"(a3) : "r"(addr));
            }
#pragma unroll
            for (int nb2 = 0; nb2 < 4; nb2++) { // n16 blocks
                uint32_t b0, b1, b2, b3;
                uint32_t off = (uint32_t)((ks * 16 + (lane & 15)) * 128 + nb2 * 32 + (lane >> 4) * 16);
                uint32_t addr = wsm_base + SWZ(off);
                asm volatile("ldmatrix.sync.aligned.m8n8.x4.trans.shared.b16 {%0,%1,%2,%3}, [%4];"
                             : "=r"(b0), "=r"(b1), "=r"(b2), "=r"(b3) : "r"(addr));
                float* c = acc[2 * nb2];
                asm volatile("mma.sync.aligned.m16n8k16.row.col.f32.f16.f16.f32 "
                             "{%0,%1,%2,%3}, {%4,%5,%6,%7}, {%8,%9}, {%0,%1,%2,%3};"
                             : "+f"(c[0]), "+f"(c[1]), "+f"(c[2]), "+f"(c[3])
                             : "r"(a0), "r"(a1), "r"(a2), "r"(a3), "r"(b0), "r"(b1));
                float* c2 = acc[2 * nb2 + 1];
                asm volatile("mma.sync.aligned.m16n8k16.row.col.f32.f16.f16.f32 "
                             "{%0,%1,%2,%3}, {%4,%5,%6,%7}, {%8,%9}, {%0,%1,%2,%3};"
                             : "+f"(c2[0]), "+f"(c2[1]), "+f"(c2[2]), "+f"(c2[3])
                             : "r"(a0), "r"(a1), "r"(a2), "r"(a3), "r"(b2), "r"(b3));
            }
        }
        __syncthreads();
    }

    // epilogue: C frag (m16n8): lane l -> rows l/4 and l/4+8, cols (l%4)*2,+1
    int r0 = row0 + warp * 16 + (lane >> 2);
    int c0 = (lane & 3) * 2;
#pragma unroll
    for (int nb = 0; nb < 8; nb++) {
        if (r0 < NNODES)
            *reinterpret_cast<__half2*>(&Hh[(size_t)r0 * HID + nb * 8 + c0]) =
                __floats2half2_rn(acc[nb][0], acc[nb][1]);
        if (r0 + 8 < NNODES)
            *reinterpret_cast<__half2*>(&Hh[(size_t)(r0 + 8) * HID + nb * 8 + c0]) =
                __floats2half2_rn(acc[nb][2], acc[nb][3]);
    }
}

// ---------------- GEMM2: f32x2 FMA (R3-proven), fp16 out ----------------
template <int K, int NO>
__global__ void __launch_bounds__(256) k_gemm(const float* __restrict__ X,
                                              const float* __restrict__ W,
                                              __half* __restrict__ Hh) {
    constexpr int KT  = 32;
    constexpr int CG  = NO / 16;
    constexpr int TPG = 256 / CG;
    constexpr int RR  = TPG * 2;

    __shared__ __align__(16) float xs[RR * (KT + 1)];
    __shared__ __align__(16) float ws[KT * NO];

    const int tid  = threadIdx.x;
    const int r    = tid % TPG;
    const int cg   = tid / TPG;
    const int row0 = blockIdx.x * RR;

    uint64_t acc0[8], acc1[8];
#pragma unroll
    for (int p = 0; p < 8; p++) { acc0[p] = 0; acc1[p] = 0; }

    for (int kt = 0; kt < K; kt += KT) {
        for (int idx = tid; idx < RR * KT; idx += 256) {
            int rr = idx / KT, kk = idx % KT;
            int gr = row0 + rr;
            xs[rr * (KT + 1) + kk] = (gr < NNODES) ? X[(size_t)gr * K + kt + kk] : 0.0f;
        }
        for (int idx = tid; idx < KT * NO; idx += 256)
            ws[idx] = W[(size_t)kt * NO + idx];
        __syncthreads();

#pragma unroll
        for (int k = 0; k < KT; k++) {
            float xv0 = xs[r * (KT + 1) + k];
            float xv1 = xs[(r + TPG) * (KT + 1) + k];
            uint64_t xa, xb;
            asm("mov.b64 %0, {%1, %1};" : "=l"(xa) : "f"(xv0));
            asm("mov.b64 %0, {%1, %1};" : "=l"(xb) : "f"(xv1));
            const uint64_t* wrow = reinterpret_cast<const uint64_t*>(&ws[k * NO + cg * 16]);
#pragma unroll
            for (int p = 0; p < 8; p++) {
                uint64_t w = wrow[p];
                asm("fma.rn.f32x2 %0, %1, %2, %0;" : "+l"(acc0[p]) : "l"(xa), "l"(w));
                asm("fma.rn.f32x2 %0, %1, %2, %0;" : "+l"(acc1[p]) : "l"(xb), "l"(w));
            }
        }
        __syncthreads();
    }

#pragma unroll
    for (int i = 0; i < 2; i++) {
        int row = row0 + r + i * TPG;
        uint64_t* a = (i == 0) ? acc0 : acc1;
        if (row < NNODES) {
            uint32_t hv[8];
#pragma unroll
            for (int p = 0; p < 8; p++) {
                float lo, hi;
                asm("mov.b64 {%0, %1}, %2;" : "=f"(lo), "=f"(hi) : "l"(a[p]));
                __half2 h2v = __floats2half2_rn(lo, hi);
                hv[p] = *reinterpret_cast<uint32_t*>(&h2v);
            }
            uint4* o = reinterpret_cast<uint4*>(&Hh[(size_t)row * NO + cg * 16]);
            o[0] = make_uint4(hv[0], hv[1], hv[2], hv[3]);
            o[1] = make_uint4(hv[4], hv[5], hv[6], hv[7]);
        }
    }
}

// ---------------- gather aggregation: 2 warps per node, 8-wide batches ----------------
__global__ void __launch_bounds__(256) k_agg1(const float* __restrict__ b1,
                                              float* __restrict__ h1r) {
    __shared__ float2 spart[4][32];
    int wid  = threadIdx.x >> 5;
    int node = blockIdx.x * 4 + (wid >> 1);
    int half = wid & 1;
    int lane = threadIdx.x & 31;
    int beg = g_rowptr[node], end = g_rowptr[node + 1];
    int mid = (beg + end) >> 1;
    int lo = half ? mid : beg;
    int hi = half ? end : mid;

    const char* h1b = (const char*)g_h1;
    float2 acc = make_float2(0.0f, 0.0f);
    int j = lo;
    for (; j + 8 <= hi; j += 8) {
        uint64_t q[8];
#pragma unroll
        for (int t = 0; t < 8; t++) q[t] = g_csr[j + t];
#pragma unroll
        for (int t = 0; t < 8; t++) {
            float nrm = __uint_as_float((uint32_t)(q[t] >> 32));
            float2 vv = __half22float2(
                *reinterpret_cast<const __half2*>(h1b + (uint32_t)q[t] + lane * 4));
            acc.x = fmaf(nrm, vv.x, acc.x);
            acc.y = fmaf(nrm, vv.y, acc.y);
        }
    }
    for (; j < hi; j++) {
        uint64_t q = g_csr[j];
        float nrm = __uint_as_float((uint32_t)(q >> 32));
        float2 vv = __half22float2(
            *reinterpret_cast<const __half2*>(h1b + (uint32_t)q + lane * 4));
        acc.x = fmaf(nrm, vv.x, acc.x);
        acc.y = fmaf(nrm, vv.y, acc.y);
    }

    if (half) spart[wid >> 1][lane] = acc;
    __syncthreads();
    if (!half) {
        float dn = g_dinv[node];
        float sc = dn * dn;
        float2 hv = __half22float2(
            *reinterpret_cast<const __half2*>(&g_h1[(size_t)node * HID + lane * 2]));
        float2 bv = *reinterpret_cast<const float2*>(&b1[lane * 2]);
        float2 o = spart[wid >> 1][lane];
        acc.x += o.x + fmaf(sc, hv.x, bv.x);
        acc.y += o.y + fmaf(sc, hv.y, bv.y);
        *reinterpret_cast<float2*>(&h1r[(size_t)node * HID + lane * 2]) =
            make_float2(fmaxf(acc.x, 0.0f), fmaxf(acc.y, 0.0f));
    }
}

__global__ void __launch_bounds__(256) k_agg2(const float* __restrict__ b2,
                                              float* __restrict__ out) {
    __shared__ float spart[4][32];
    int wid  = threadIdx.x >> 5;
    int node = blockIdx.x * 4 + (wid >> 1);
    int half = wid & 1;
    int lane = threadIdx.x & 31;
    int beg = g_rowptr[node], end = g_rowptr[node + 1];
    int mid = (beg + end) >> 1;
    int lo = half ? mid : beg;
    int hi = half ? end : mid;

    const char* h2b = (const char*)g_h2;
    float acc = 0.0f;
    int j = lo;
    for (; j + 8 <= hi; j += 8) {
        uint64_t q[8];
#pragma unroll
        for (int t = 0; t < 8; t++) q[t] = g_csr[j + t];
#pragma unroll
        for (int t = 0; t < 8; t++) {
            float nrm = __uint_as_float((uint32_t)(q[t] >> 32));
            float v = __half2float(
                *reinterpret_cast<const __half*>(h2b + (((uint32_t)q[t]) >> 1) + lane * 2));
            acc = fmaf(nrm, v, acc);
        }
    }
    for (; j < hi; j++) {
        uint64_t q = g_csr[j];
        float nrm = __uint_as_float((uint32_t)(q >> 32));
        float v = __half2float(
            *reinterpret_cast<const __half*>(h2b + (((uint32_t)q) >> 1) + lane * 2));
        acc = fmaf(nrm, v, acc);
    }

    if (half) spart[wid >> 1][lane] = acc;
    __syncthreads();
    if (!half) {
        float dn = g_dinv[node];
        acc += spart[wid >> 1][lane];
        acc += fmaf(dn * dn, __half2float(g_h2[(size_t)node * OUTD + lane]), b2[lane]);
        out[(size_t)node * OUTD + lane] = acc;
    }
}

// ---------------- launch ----------------
extern "C" void kernel_launch(void* const* d_in, const int* in_sizes, int n_in,
                              void* d_out, int out_size) {
    const float* x  = (const float*)d_in[0];
    const void*  ei = d_in[1];
    const float* W1 = (const float*)d_in[2];
    const float* b1 = (const float*)d_in[3];
    const float* W2 = (const float*)d_in[4];
    const float* b2 = (const float*)d_in[5];
    float*       out = (float*)d_out;

    void *ph1, *ph1r, *ph2;
    cudaGetSymbolAddress(&ph1,  g_h1);
    cudaGetSymbolAddress(&ph1r, g_h1r);
    cudaGetSymbolAddress(&ph2,  g_h2);
    __half* h1  = (__half*)ph1;
    float*  h1r = (float*)ph1r;
    __half* h2  = (__half*)ph2;

    const int NT = 256;
    const int EB = (NEDGES + NT - 1) / NT;
    const int NB = (NNODES + NT - 1) / NT;

    // graph normalization + CSR build
    k_init<<<NB, NT>>>((const int*)ei);
    k_count<<<EB, NT>>>(ei);
    k_scan_block<<<NSCANB, 1024>>>();
    k_scan_add<<<NSCANB, 1024>>>();
    k_fill<<<EB, NT>>>(ei);

    // layer 1: h1 = fp16(X @ W1) via HMMA ; h1r = relu(selfloop + b1 + gather)
    k_gemm1<<<(NNODES + 127) / 128, NT>>>(x, W1, h1);
    k_agg1<<<NNODES / 4, NT>>>(b1, h1r);

    // layer 2: h2 = fp16(h1r @ W2) ; out = selfloop + b2 + gather
    k_gemm<HID, OUTD><<<(NNODES + 255) / 256, NT>>>(h1r, W2, h2);
    k_agg2<<<NNODES / 4, NT>>>(b2, out);
}

// round 8
// speedup vs baseline: 1.4208x; 1.1556x over previous
#include <cuda_runtime.h>
#include <cuda_fp16.h>
#include <cstdint>

#define NNODES 100000
#define NEDGES 3200000
#define INDIM 256
#define HID 64
#define OUTD 32
#define NSCANB 98   // ceil(100000/1024)

// ---------------- scratch ----------------
__device__ __align__(128) int      g_deg[NNODES];
__device__ __align__(128) float    g_dinv[NNODES];
__device__ __align__(128) int      g_rowptr[NNODES + 1];
__device__ __align__(128) int      g_cursor[NNODES];
__device__ __align__(128) int      g_bsum[NSCANB];
__device__ __align__(128) uint64_t g_csr[NEDGES];                 // (norm_bits<<32) | (src*128)
__device__ __align__(128) __half   g_h1[(size_t)NNODES * HID];    // fp16: X@W1
__device__ __align__(128) __half   g_h1r[(size_t)NNODES * HID];   // fp16: relu(agg1)
__device__ __align__(128) __half   g_h2[(size_t)NNODES * OUTD];   // fp16: h1r@W2
__device__ int g_is64;

// ---------------- detect index dtype ----------------
__global__ void k_detect(const int* __restrict__ ei32) {
    if (threadIdx.x == 0) {
        int acc = 0;
        for (int k = 0; k < 512; k++) acc |= ei32[2 * k + 1];
        for (int k = 0; k < 512; k++) acc |= ei32[2 * (NEDGES / 2 + k) + 1];
        g_is64 = (acc == 0) ? 1 : 0;
    }
}

__device__ __forceinline__ void load_edge(const void* ei, int e, int& s, int& d) {
    if (g_is64) {
        const long long* p = (const long long*)ei;
        s = (int)p[e];
        d = (int)p[NEDGES + e];
    } else {
        const int* p = (const int*)ei;
        s = p[e];
        d = p[NEDGES + e];
    }
}

__global__ void k_count(const void* __restrict__ ei) {
    int e = blockIdx.x * blockDim.x + threadIdx.x;
    if (e >= NEDGES) return;
    int s, d;
    load_edge(ei, e, s, d);
    atomicAdd(&g_deg[d], 1);
}

// ---------------- scan ----------------
__global__ void k_scan_block() {
    __shared__ int s[1024];
    int t = threadIdx.x;
    int gi = blockIdx.x * 1024 + t;
    int v = (gi < NNODES) ? g_deg[gi] : 0;
    s[t] = v;
    __syncthreads();
#pragma unroll
    for (int off = 1; off < 1024; off <<= 1) {
        int a = (t >= off) ? s[t - off] : 0;
        __syncthreads();
        s[t] += a;
        __syncthreads();
    }
    if (gi <= NNODES) g_rowptr[gi] = s[t] - v;
    if (t == 1023) g_bsum[blockIdx.x] = s[1023];
}

__global__ void k_scan_add() {
    __shared__ int spfx;
    int b = blockIdx.x;
    int t = threadIdx.x;
    if (t < 32) {
        int s = 0;
        for (int i = t; i < b; i += 32) s += g_bsum[i];
#pragma unroll
        for (int off = 16; off > 0; off >>= 1) s += __shfl_xor_sync(0xffffffffu, s, off);
        if (t == 0) spfx = s;
    }
    __syncthreads();
    int i = b * 1024 + t;
    if (i < NNODES) {
        int rp = g_rowptr[i] + spfx;
        g_rowptr[i] = rp;
        g_cursor[i] = rp;
        g_dinv[i]   = rsqrtf((float)g_deg[i] + 1.0f);
    }
    if (i == 0) g_rowptr[NNODES] = NEDGES;
}

// ---------------- fill CSR ----------------
__global__ void k_fill(const void* __restrict__ ei) {
    int e = blockIdx.x * blockDim.x + threadIdx.x;
    if (e >= NEDGES) return;
    int s, d;
    load_edge(ei, e, s, d);
    int pos = atomicAdd(&g_cursor[d], 1);
    float nrm = g_dinv[s] * g_dinv[d];
    g_csr[pos] = ((uint64_t)__float_as_uint(nrm) << 32) | (uint32_t)(s * 128);
}

// ---------------- HMMA GEMM: Hh[M,NO] = X[M,K] @ W[K,NO] ----------------
// 256 thr = 8 warps (warp owns m16, M-tile 128). K-tiles of 64. SW128-swizzled smem.
#define SWZ(off) ((off) ^ (((off) >> 3) & 0x70))
template <int K, int NO, bool FP32IN>
__global__ void __launch_bounds__(256) k_hmma(const void* __restrict__ Xv,
                                              const float* __restrict__ W,
                                              __half* __restrict__ Hh) {
    __shared__ __align__(16) __half xs[128 * 64];   // 16 KB (128B rows)
    __shared__ __align__(16) __half wsm[64 * 64];   // 8 KB  (128B rows)
    const int tid  = threadIdx.x;
    const int warp = tid >> 5;
    const int lane = tid & 31;
    const int row0 = blockIdx.x * 128;
    constexpr int NB = NO / 8;

    float acc[NB][4];
#pragma unroll
    for (int n = 0; n < NB; n++)
#pragma unroll
        for (int q = 0; q < 4; q++) acc[n][q] = 0.0f;

    uint32_t xs_base  = (uint32_t)__cvta_generic_to_shared(xs);
    uint32_t wsm_base = (uint32_t)__cvta_generic_to_shared(wsm);

    for (int kt = 0; kt < K / 64; kt++) {
        if (FP32IN) {
            const float* X = (const float*)Xv;
            for (int idx = tid; idx < 128 * 32; idx += 256) {
                int row = idx >> 5, cp = idx & 31;
                int gr = row0 + row;
                float2 v = (gr < NNODES)
                    ? *reinterpret_cast<const float2*>(&X[(size_t)gr * K + kt * 64 + cp * 2])
                    : make_float2(0.0f, 0.0f);
                uint32_t off = SWZ((uint32_t)(row * 128 + cp * 4));
                *reinterpret_cast<__half2*>((char*)xs + off) = __floats2half2_rn(v.x, v.y);
            }
        } else {
            const __half* X = (const __half*)Xv;
            for (int idx = tid; idx < 128 * 8; idx += 256) {
                int row = idx >> 3, cp = idx & 7;
                int gr = row0 + row;
                uint4 v = (gr < NNODES)
                    ? *reinterpret_cast<const uint4*>(&X[(size_t)gr * K + kt * 64 + cp * 8])
                    : make_uint4(0, 0, 0, 0);
                uint32_t off = SWZ((uint32_t)(row * 128 + cp * 16));
                *reinterpret_cast<uint4*>((char*)xs + off) = v;
            }
        }
        for (int idx = tid; idx < 64 * (NO / 2); idx += 256) {
            int row = idx / (NO / 2), cp = idx % (NO / 2);
            float2 v = *reinterpret_cast<const float2*>(&W[(size_t)(kt * 64 + row) * NO + cp * 2]);
            uint32_t off = SWZ((uint32_t)(row * 128 + cp * 4));
            *reinterpret_cast<__half2*>((char*)wsm + off) = __floats2half2_rn(v.x, v.y);
        }
        __syncthreads();

#pragma unroll
        for (int ks = 0; ks < 4; ks++) {
            uint32_t a0, a1, a2, a3;
            {
                uint32_t off = (uint32_t)((warp * 16 + (lane & 15)) * 128 + ks * 32 + (lane >> 4) * 16);
                uint32_t addr = xs_base + SWZ(off);
                asm volatile("ldmatrix.sync.aligned.m8n8.x4.shared.b16 {%0,%1,%2,%3}, [%4];"
                             : "=r"(a0), "=r"(a1), "=r"(a2), "=r"(a3) : "r"(addr));
            }
#pragma unroll
            for (int nb2 = 0; nb2 < NO / 16; nb2++) {
                uint32_t b0, b1, b2, b3;
                uint32_t off = (uint32_t)((ks * 16 + (lane & 15)) * 128 + nb2 * 32 + (lane >> 4) * 16);
                uint32_t addr = wsm_base + SWZ(off);
                asm volatile("ldmatrix.sync.aligned.m8n8.x4.trans.shared.b16 {%0,%1,%2,%3}, [%4];"
                             : "=r"(b0), "=r"(b1), "=r"(b2), "=r"(b3) : "r"(addr));
                float* c = acc[2 * nb2];
                asm volatile("mma.sync.aligned.m16n8k16.row.col.f32.f16.f16.f32 "
                             "{%0,%1,%2,%3}, {%4,%5,%6,%7}, {%8,%9}, {%0,%1,%2,%3};"
                             : "+f"(c[0]), "+f"(c[1]), "+f"(c[2]), "+f"(c[3])
                             : "r"(a0), "r"(a1), "r"(a2), "r"(a3), "r"(b0), "r"(b1));
                float* c2 = acc[2 * nb2 + 1];
                asm volatile("mma.sync.aligned.m16n8k16.row.col.f32.f16.f16.f32 "
                             "{%0,%1,%2,%3}, {%4,%5,%6,%7}, {%8,%9}, {%0,%1,%2,%3};"
                             : "+f"(c2[0]), "+f"(c2[1]), "+f"(c2[2]), "+f"(c2[3])
                             : "r"(a0), "r"(a1), "r"(a2), "r"(a3), "r"(b2), "r"(b3));
            }
        }
        __syncthreads();
    }

    int r0 = row0 + warp * 16 + (lane >> 2);
    int c0 = (lane & 3) * 2;
#pragma unroll
    for (int nb = 0; nb < NB; nb++) {
        if (r0 < NNODES)
            *reinterpret_cast<__half2*>(&Hh[(size_t)r0 * NO + nb * 8 + c0]) =
                __floats2half2_rn(acc[nb][0], acc[nb][1]);
        if (r0 + 8 < NNODES)
            *reinterpret_cast<__half2*>(&Hh[(size_t)(r0 + 8) * NO + nb * 8 + c0]) =
                __floats2half2_rn(acc[nb][2], acc[nb][3]);
    }
}

// ---------------- gather aggregation: 2 warps per node, 8-wide batches ----------------
__global__ void __launch_bounds__(256) k_agg1(const float* __restrict__ b1,
                                              __half* __restrict__ h1r) {
    __shared__ float2 spart[4][32];
    int wid  = threadIdx.x >> 5;
    int node = blockIdx.x * 4 + (wid >> 1);
    int half = wid & 1;
    int lane = threadIdx.x & 31;
    int beg = g_rowptr[node], end = g_rowptr[node + 1];
    int mid = (beg + end) >> 1;
    int lo = half ? mid : beg;
    int hi = half ? end : mid;

    const char* h1b = (const char*)g_h1;
    float2 acc = make_float2(0.0f, 0.0f);
    int j = lo;
    for (; j + 8 <= hi; j += 8) {
        uint64_t q[8];
#pragma unroll
        for (int t = 0; t < 8; t++) q[t] = g_csr[j + t];
#pragma unroll
        for (int t = 0; t < 8; t++) {
            float nrm = __uint_as_float((uint32_t)(q[t] >> 32));
            float2 vv = __half22float2(
                *reinterpret_cast<const __half2*>(h1b + (uint32_t)q[t] + lane * 4));
            acc.x = fmaf(nrm, vv.x, acc.x);
            acc.y = fmaf(nrm, vv.y, acc.y);
        }
    }
    for (; j < hi; j++) {
        uint64_t q = g_csr[j];
        float nrm = __uint_as_float((uint32_t)(q >> 32));
        float2 vv = __half22float2(
            *reinterpret_cast<const __half2*>(h1b + (uint32_t)q + lane * 4));
        acc.x = fmaf(nrm, vv.x, acc.x);
        acc.y = fmaf(nrm, vv.y, acc.y);
    }

    if (half) spart[wid >> 1][lane] = acc;
    __syncthreads();
    if (!half) {
        float dn = g_dinv[node];
        float sc = dn * dn;
        float2 hv = __half22float2(
            *reinterpret_cast<const __half2*>(&g_h1[(size_t)node * HID + lane * 2]));
        float2 bv = *reinterpret_cast<const float2*>(&b1[lane * 2]);
        float2 o = spart[wid >> 1][lane];
        acc.x += o.x + fmaf(sc, hv.x, bv.x);
        acc.y += o.y + fmaf(sc, hv.y, bv.y);
        *reinterpret_cast<__half2*>(&h1r[(size_t)node * HID + lane * 2]) =
            __floats2half2_rn(fmaxf(acc.x, 0.0f), fmaxf(acc.y, 0.0f));
    }
}

__global__ void __launch_bounds__(256) k_agg2(const float* __restrict__ b2,
                                              float* __restrict__ out) {
    __shared__ float spart[4][32];
    int wid  = threadIdx.x >> 5;
    int node = blockIdx.x * 4 + (wid >> 1);
    int half = wid & 1;
    int lane = threadIdx.x & 31;
    int beg = g_rowptr[node], end = g_rowptr[node + 1];
    int mid = (beg + end) >> 1;
    int lo = half ? mid : beg;
    int hi = half ? end : mid;

    const char* h2b = (const char*)g_h2;
    float acc = 0.0f;
    int j = lo;
    for (; j + 8 <= hi; j += 8) {
        uint64_t q[8];
#pragma unroll
        for (int t = 0; t < 8; t++) q[t] = g_csr[j + t];
#pragma unroll
        for (int t = 0; t < 8; t++) {
            float nrm = __uint_as_float((uint32_t)(q[t] >> 32));
            float v = __half2float(
                *reinterpret_cast<const __half*>(h2b + (((uint32_t)q[t]) >> 1) + lane * 2));
            acc = fmaf(nrm, v, acc);
        }
    }
    for (; j < hi; j++) {
        uint64_t q = g_csr[j];
        float nrm = __uint_as_float((uint32_t)(q >> 32));
        float v = __half2float(
            *reinterpret_cast<const __half*>(h2b + (((uint32_t)q) >> 1) + lane * 2));
        acc = fmaf(nrm, v, acc);
    }

    if (half) spart[wid >> 1][lane] = acc;
    __syncthreads();
    if (!half) {
        float dn = g_dinv[node];
        acc += spart[wid >> 1][lane];
        acc += fmaf(dn * dn, __half2float(g_h2[(size_t)node * OUTD + lane]), b2[lane]);
        out[(size_t)node * OUTD + lane] = acc;
    }
}

// ---------------- launch ----------------
extern "C" void kernel_launch(void* const* d_in, const int* in_sizes, int n_in,
                              void* d_out, int out_size) {
    const float* x  = (const float*)d_in[0];
    const void*  ei = d_in[1];
    const float* W1 = (const float*)d_in[2];
    const float* b1 = (const float*)d_in[3];
    const float* W2 = (const float*)d_in[4];
    const float* b2 = (const float*)d_in[5];
    float*       out = (float*)d_out;

    void *ph1, *ph1r, *ph2, *pdeg;
    cudaGetSymbolAddress(&ph1,  g_h1);
    cudaGetSymbolAddress(&ph1r, g_h1r);
    cudaGetSymbolAddress(&ph2,  g_h2);
    cudaGetSymbolAddress(&pdeg, g_deg);
    __half* h1  = (__half*)ph1;
    __half* h1r = (__half*)ph1r;
    __half* h2  = (__half*)ph2;

    static cudaStream_t s2 = nullptr;
    static cudaEvent_t evF = nullptr, evJ = nullptr;
    if (s2 == nullptr) {
        cudaStreamCreateWithFlags(&s2, cudaStreamNonBlocking);
        cudaEventCreateWithFlags(&evF, cudaEventDisableTiming);
        cudaEventCreateWithFlags(&evJ, cudaEventDisableTiming);
    }

    const int NT = 256;
    const int EB = (NEDGES + NT - 1) / NT;
    const int GB = (NNODES + 127) / 128;   // 782 HMMA blocks

    // fork: GEMM1 (depends only on x,W1) runs parallel to the CSR build
    cudaEventRecord(evF, 0);
    cudaStreamWaitEvent(s2, evF, 0);
    k_hmma<INDIM, HID, true><<<GB, NT, 0, s2>>>(x, W1, h1);
    cudaEventRecord(evJ, s2);

    // CSR build on the main stream
    k_detect<<<1, 32>>>((const int*)ei);
    cudaMemsetAsync(pdeg, 0, NNODES * sizeof(int));
    k_count<<<EB, NT>>>(ei);
    k_scan_block<<<NSCANB, 1024>>>();
    k_scan_add<<<NSCANB, 1024>>>();
    k_fill<<<EB, NT>>>(ei);

    // join, then layer 1 aggregate + layer 2
    cudaStreamWaitEvent(0, evJ, 0);
    k_agg1<<<NNODES / 4, NT>>>(b1, h1r);
    k_hmma<HID, OUTD, false><<<GB, NT>>>(h1r, W2, h2);
    k_agg2<<<NNODES / 4, NT>>>(b2, out);
}